// round 2
// baseline (speedup 1.0000x reference)
#include <cuda_runtime.h>

#define NN   50000
#define EE   800000
#define FIN  64
#define HID  128
#define NCLS 10
#define NG   128
#define KTOP 400000
#define MAX_TIES 4096

struct SelState {
    unsigned prefix;
    int kk;
    unsigned threshold;
    int needed;
    int tie_count;
};

struct __align__(16) Scratch {
    float h [(size_t)NN * HID];
    float Ai[(size_t)NN * HID];
    float At[(size_t)NN * HID];
    float Ar[(size_t)NN * HID];
    float T1[(size_t)NN * HID];
    float T2[(size_t)NN * HID];
    float X1[(size_t)NN * HID];
    float X2[(size_t)NN * HID];
    float ew[EE];
    unsigned char flag[EE];
    unsigned hist[2048];
    int tie[MAX_TIES];
    float pool[NG * HID];
    SelState st;
};
__device__ Scratch g_s;

// ---------------------------------------------------------------------------
// vector fp32 reduction to global (sm_90+)
// ---------------------------------------------------------------------------
__device__ __forceinline__ void red4(float* addr, float4 v) {
    asm volatile("red.global.add.v4.f32 [%0], {%1,%2,%3,%4};"
                 :: "l"(addr), "f"(v.x), "f"(v.y), "f"(v.z), "f"(v.w)
                 : "memory");
}

__device__ __forceinline__ unsigned fkey(float f) {
    unsigned u = __float_as_uint(f);
    return (u & 0x80000000u) ? ~u : (u | 0x80000000u);
}

// ---------------------------------------------------------------------------
// zero / init
// ---------------------------------------------------------------------------
__global__ void zero_init(Scratch* s) {
    size_t idx = (size_t)blockIdx.x * blockDim.x + threadIdx.x;
    size_t stride = (size_t)gridDim.x * blockDim.x;
    const size_t nf4 = (size_t)NN * HID / 4;
    float4 z = make_float4(0.f, 0.f, 0.f, 0.f);
    float4* ai = (float4*)s->Ai;
    float4* at = (float4*)s->At;
    float4* ar = (float4*)s->Ar;
    for (size_t i = idx; i < nf4; i += stride) {
        ai[i] = z; at[i] = z; ar[i] = z;
    }
    if (idx < (size_t)NG * HID / 4) ((float4*)s->pool)[idx] = z;
    if (idx < 2048) s->hist[idx] = 0;
    if (idx == 0) {
        s->st.prefix = 0;
        s->st.kk = KTOP;
        s->st.tie_count = 0;
    }
}

// ---------------------------------------------------------------------------
// GEMM: C[M x 128] = epilogue( (A + optional 2*H)[M x K] @ W[K x 128] + bias )
// Block tile 64 x 128, BK=16, 128 threads, 8x8 microtile split 2x2 quadrants.
// Double-buffered smem; dual-problem via blockIdx.y.
// ---------------------------------------------------------------------------
struct GArgs {
    const float* A;
    const float* W;
    const float* bias;
    float* C;
};

template<int K, bool ADD2H, bool RELU>
__global__ __launch_bounds__(128)
void gemm64(GArgs g0, GArgs g1, const float* __restrict__ Hh, int M)
{
    __shared__ __align__(16) float As[2][16][64];
    __shared__ __align__(16) float Bs[2][16][128];

    GArgs g = (blockIdx.y == 1) ? g1 : g0;
    const float* __restrict__ A = g.A;
    const float* __restrict__ W = g.W;

    const int m0 = blockIdx.x * 64;
    const int t  = threadIdx.x;
    const int tx = t & 15;          // n quadrant selector (16)
    const int ty = t >> 4;          // m quadrant selector (8)

    // A-load mapping: 2 float4 per thread
    const int ar0 = t >> 2;         // 0..31 (l=0), +32 (l=1)
    const int akc = (t & 3) * 4;    // k sub-column within 16
    // B-load mapping: 4 float4 per thread
    const int bkr = t >> 5;         // 0..3 (+4*l)
    const int bc4 = (t & 31) * 4;   // n column *4

    float acc[8][8];
#pragma unroll
    for (int i = 0; i < 8; i++)
#pragma unroll
        for (int j = 0; j < 8; j++) acc[i][j] = 0.f;

    float4 av[2], bv[4];

    auto ldg_tiles = [&](int k0) {
#pragma unroll
        for (int l = 0; l < 2; l++) {
            int m = m0 + ar0 + l * 32;
            float4 v = make_float4(0.f, 0.f, 0.f, 0.f);
            if (m < M) {
                v = *(const float4*)&A[(size_t)m * K + k0 + akc];
                if (ADD2H) {
                    float4 hv = *(const float4*)&Hh[(size_t)m * K + k0 + akc];
                    v.x += 2.f * hv.x; v.y += 2.f * hv.y;
                    v.z += 2.f * hv.z; v.w += 2.f * hv.w;
                }
            }
            av[l] = v;
        }
#pragma unroll
        for (int l = 0; l < 4; l++)
            bv[l] = *(const float4*)&W[(size_t)(k0 + bkr + l * 4) * 128 + bc4];
    };

    auto sts_tiles = [&](int buf) {
#pragma unroll
        for (int l = 0; l < 2; l++) {
            int r = ar0 + l * 32;
            As[buf][akc + 0][r] = av[l].x;
            As[buf][akc + 1][r] = av[l].y;
            As[buf][akc + 2][r] = av[l].z;
            As[buf][akc + 3][r] = av[l].w;
        }
#pragma unroll
        for (int l = 0; l < 4; l++)
            *(float4*)&Bs[buf][bkr + l * 4][bc4] = bv[l];
    };

    auto compute = [&](int buf) {
#pragma unroll
        for (int kk = 0; kk < 16; kk++) {
            float4 a0 = *(const float4*)&As[buf][kk][ty * 4];
            float4 a1 = *(const float4*)&As[buf][kk][32 + ty * 4];
            float4 b0 = *(const float4*)&Bs[buf][kk][tx * 4];
            float4 b1 = *(const float4*)&Bs[buf][kk][64 + tx * 4];
            float aa[8] = {a0.x, a0.y, a0.z, a0.w, a1.x, a1.y, a1.z, a1.w};
            float bb[8] = {b0.x, b0.y, b0.z, b0.w, b1.x, b1.y, b1.z, b1.w};
#pragma unroll
            for (int i = 0; i < 8; i++)
#pragma unroll
                for (int j = 0; j < 8; j++)
                    acc[i][j] += aa[i] * bb[j];
        }
    };

    ldg_tiles(0);
    sts_tiles(0);
    __syncthreads();
    int buf = 0;
    for (int k0 = 16; k0 < K; k0 += 16) {
        ldg_tiles(k0);
        compute(buf);
        sts_tiles(buf ^ 1);
        __syncthreads();
        buf ^= 1;
    }
    compute(buf);

    const float4 bias0 = *(const float4*)&g.bias[tx * 4];
    const float4 bias1 = *(const float4*)&g.bias[64 + tx * 4];
#pragma unroll
    for (int gi = 0; gi < 2; gi++) {
#pragma unroll
        for (int i = 0; i < 4; i++) {
            int m = m0 + gi * 32 + ty * 4 + i;
            if (m >= M) continue;
            int ri = gi * 4 + i;
            float4 v0, v1;
            v0.x = acc[ri][0] + bias0.x; v0.y = acc[ri][1] + bias0.y;
            v0.z = acc[ri][2] + bias0.z; v0.w = acc[ri][3] + bias0.w;
            v1.x = acc[ri][4] + bias1.x; v1.y = acc[ri][5] + bias1.y;
            v1.z = acc[ri][6] + bias1.z; v1.w = acc[ri][7] + bias1.w;
            if (RELU) {
                v0.x = fmaxf(v0.x, 0.f); v0.y = fmaxf(v0.y, 0.f);
                v0.z = fmaxf(v0.z, 0.f); v0.w = fmaxf(v0.w, 0.f);
                v1.x = fmaxf(v1.x, 0.f); v1.y = fmaxf(v1.y, 0.f);
                v1.z = fmaxf(v1.z, 0.f); v1.w = fmaxf(v1.w, 0.f);
            }
            *(float4*)&g.C[(size_t)m * 128 + tx * 4] = v0;
            *(float4*)&g.C[(size_t)m * 128 + 64 + tx * 4] = v1;
        }
    }
}

// ---------------------------------------------------------------------------
// scatter (weight 1): agg[col] += h[row]
// ---------------------------------------------------------------------------
__global__ void scatter_ones(const int* __restrict__ row, const int* __restrict__ col,
                             const float* __restrict__ h, float* __restrict__ out)
{
    int e = blockIdx.x * 8 + (threadIdx.x >> 5);
    if (e >= EE) return;
    int lane = threadIdx.x & 31;
    int r = __ldg(&row[e]);
    int c = __ldg(&col[e]);
    float4 v = *(const float4*)(h + (size_t)r * HID + lane * 4);
    red4(out + (size_t)c * HID + lane * 4, v);
}

// ---------------------------------------------------------------------------
// per-edge dot: ew[e] = <X[row], X[col]>, fused radix histogram pass 0
// ---------------------------------------------------------------------------
__global__ void ew_kernel(const int* __restrict__ row, const int* __restrict__ col,
                          const float* __restrict__ X, float* __restrict__ ew,
                          unsigned* __restrict__ hist)
{
    int e = blockIdx.x * 8 + (threadIdx.x >> 5);
    if (e >= EE) return;
    int lane = threadIdx.x & 31;
    int r = __ldg(&row[e]);
    int c = __ldg(&col[e]);
    float4 a = *(const float4*)(X + (size_t)r * HID + lane * 4);
    float4 b = *(const float4*)(X + (size_t)c * HID + lane * 4);
    float s = a.x * b.x + a.y * b.y + a.z * b.z + a.w * b.w;
#pragma unroll
    for (int off = 16; off >= 1; off >>= 1)
        s += __shfl_xor_sync(0xFFFFFFFFu, s, off);
    if (lane == 0) {
        ew[e] = s;
        atomicAdd(&hist[fkey(s) >> 21], 1u);
    }
}

// ---------------------------------------------------------------------------
// radix-select histogram passes 1 and 2
// ---------------------------------------------------------------------------
__global__ void hist_kernel(const float* __restrict__ ew, unsigned* __restrict__ hist,
                            const SelState* __restrict__ st, int pass)
{
    __shared__ unsigned sh[2048];
    for (int i = threadIdx.x; i < 2048; i += blockDim.x) sh[i] = 0;
    __syncthreads();
    unsigned pref = st->prefix;
    int stride = gridDim.x * blockDim.x;
    for (int e = blockIdx.x * blockDim.x + threadIdx.x; e < EE; e += stride) {
        unsigned u = fkey(ew[e]);
        if (pass == 1) {
            if ((u >> 21) == pref) atomicAdd(&sh[(u >> 10) & 2047u], 1u);
        } else {
            if ((u >> 10) == pref) atomicAdd(&sh[u & 1023u], 1u);
        }
    }
    __syncthreads();
    for (int i = threadIdx.x; i < 2048; i += blockDim.x)
        if (sh[i]) atomicAdd(&hist[i], sh[i]);
}

// ---------------------------------------------------------------------------
// suffix-scan of histogram; pick bucket, update state; zeroes hist for next use
// ---------------------------------------------------------------------------
__global__ void scan_kernel(unsigned* __restrict__ hist, SelState* __restrict__ st,
                            int nbins, int bits, int last)
{
    __shared__ unsigned a[2048], b[2048];
    __shared__ int bstar;
    int tid = threadIdx.x;
    for (int i = tid; i < 2048; i += blockDim.x) {
        a[i] = (i < nbins) ? hist[i] : 0u;
        hist[i] = 0u;
    }
    __syncthreads();
    unsigned* src = a;
    unsigned* dst = b;
    for (int off = 1; off < nbins; off <<= 1) {
        for (int i = tid; i < nbins; i += blockDim.x)
            dst[i] = src[i] + ((i + off < nbins) ? src[i + off] : 0u);
        __syncthreads();
        unsigned* t = src; src = dst; dst = t;
    }
    int kk = st->kk;
    for (int i = tid; i < nbins; i += blockDim.x) {
        unsigned Si = src[i];
        unsigned Sn = (i + 1 < nbins) ? src[i + 1] : 0u;
        if (Si >= (unsigned)kk && Sn < (unsigned)kk) bstar = i;
    }
    __syncthreads();
    if (tid == 0) {
        int bs = bstar;
        unsigned greater = (bs + 1 < nbins) ? src[bs + 1] : 0u;
        st->kk = kk - (int)greater;
        st->prefix = (st->prefix << bits) | (unsigned)bs;
        if (last) {
            st->threshold = st->prefix;
            st->needed = st->kk;
        }
    }
}

// ---------------------------------------------------------------------------
// flag edges strictly above threshold; collect ties
// ---------------------------------------------------------------------------
__global__ void flag_kernel(const float* __restrict__ ew, unsigned char* __restrict__ flag,
                            int* __restrict__ tie, SelState* __restrict__ st)
{
    unsigned T = st->threshold;
    int stride = gridDim.x * blockDim.x;
    for (int e = blockIdx.x * blockDim.x + threadIdx.x; e < EE; e += stride) {
        unsigned u = fkey(ew[e]);
        flag[e] = (u > T) ? (unsigned char)1 : (unsigned char)0;
        if (u == T) {
            int p = atomicAdd(&st->tie_count, 1);
            if (p < MAX_TIES) tie[p] = e;
        }
    }
}

// ---------------------------------------------------------------------------
// pick `needed` lowest-index ties (matches jax.lax.top_k stability)
// ---------------------------------------------------------------------------
__global__ void tie_resolve(int* __restrict__ tie, unsigned char* __restrict__ flag,
                            const SelState* __restrict__ st)
{
    __shared__ int s[MAX_TIES];
    int C = st->tie_count;
    if (C > MAX_TIES) C = MAX_TIES;
    int nd = st->needed;
    int tid = threadIdx.x;
    if (C <= nd) {
        for (int i = tid; i < C; i += blockDim.x) flag[tie[i]] = 1;
        return;
    }
    for (int i = tid; i < C; i += blockDim.x) s[i] = tie[i];
    __syncthreads();
    for (int ph = 0; ph < C; ph++) {
        for (int i = 2 * tid + (ph & 1); i + 1 < C; i += 2 * blockDim.x) {
            if (s[i] > s[i + 1]) { int t = s[i]; s[i] = s[i + 1]; s[i + 1] = t; }
        }
        __syncthreads();
    }
    for (int i = tid; i < nd; i += blockDim.x) flag[s[i]] = 1;
}

// ---------------------------------------------------------------------------
// weighted scatter into top / remaining aggregates
// ---------------------------------------------------------------------------
__global__ void scatter_sel(const int* __restrict__ row, const int* __restrict__ col,
                            const float* __restrict__ h, const float* __restrict__ ew,
                            const unsigned char* __restrict__ flag,
                            float* __restrict__ At, float* __restrict__ Ar)
{
    int e = blockIdx.x * 8 + (threadIdx.x >> 5);
    if (e >= EE) return;
    int lane = threadIdx.x & 31;
    int r = __ldg(&row[e]);
    int c = __ldg(&col[e]);
    float w = __ldg(&ew[e]);
    float4 v = *(const float4*)(h + (size_t)r * HID + lane * 4);
    v.x *= w; v.y *= w; v.z *= w; v.w *= w;
    float* dst = flag[e] ? At : Ar;
    red4(dst + (size_t)c * HID + lane * 4, v);
}

// ---------------------------------------------------------------------------
// pooling: pooled[batch[n]] += x1[n] + x2[n]   (batch sorted -> run flush)
// ---------------------------------------------------------------------------
#define NPB 128
__global__ void pool_kernel(const float* __restrict__ x1, const float* __restrict__ x2,
                            const int* __restrict__ batch, float* __restrict__ pooled)
{
    int f = threadIdx.x;
    int n0 = blockIdx.x * NPB;
    if (n0 >= NN) return;
    int n1 = n0 + NPB;
    if (n1 > NN) n1 = NN;
    int cur = batch[n0];
    float acc = 0.f;
    for (int n = n0; n < n1; n++) {
        int b = batch[n];
        if (b != cur) {
            atomicAdd(&pooled[cur * HID + f], acc);
            acc = 0.f;
            cur = b;
        }
        acc += x1[(size_t)n * HID + f] + x2[(size_t)n * HID + f];
    }
    atomicAdd(&pooled[cur * HID + f], acc);
}

// ---------------------------------------------------------------------------
// head: p = relu(pooled@post_W+post_b); logits = p@ro_W+ro_b; log_softmax
// ---------------------------------------------------------------------------
__global__ void head_kernel(const float* __restrict__ pool,
                            const float* __restrict__ pW, const float* __restrict__ pb,
                            const float* __restrict__ rW, const float* __restrict__ rb,
                            float* __restrict__ out)
{
    __shared__ float rowv[HID], p[HID], lg[NCLS];
    int g = blockIdx.x, t = threadIdx.x;
    rowv[t] = pool[g * HID + t];
    __syncthreads();
    float s = pb[t];
#pragma unroll 8
    for (int k = 0; k < HID; k++) s += rowv[k] * pW[k * HID + t];
    p[t] = fmaxf(s, 0.f);
    __syncthreads();
    if (t < NCLS) {
        float s2 = rb[t];
#pragma unroll 8
        for (int k = 0; k < HID; k++) s2 += p[k] * rW[k * NCLS + t];
        lg[t] = s2;
    }
    __syncthreads();
    if (t == 0) {
        float mx = lg[0];
        for (int j = 1; j < NCLS; j++) mx = fmaxf(mx, lg[j]);
        float se = 0.f;
        for (int j = 0; j < NCLS; j++) se += expf(lg[j] - mx);
        float l = logf(se) + mx;
        for (int j = 0; j < NCLS; j++) out[g * NCLS + j] = lg[j] - l;
    }
}

// ---------------------------------------------------------------------------
// launch
// ---------------------------------------------------------------------------
extern "C" void kernel_launch(void* const* d_in, const int* in_sizes, int n_in,
                              void* d_out, int out_size)
{
    (void)in_sizes; (void)n_in; (void)out_size;
    const float* x     = (const float*)d_in[0];
    const int*   ei    = (const int*)d_in[1];
    const int*   row   = ei;
    const int*   col   = ei + EE;
    const int*   batch = (const int*)d_in[2];
    const float* preW  = (const float*)d_in[3];
    const float* preB  = (const float*)d_in[4];
    const int LW = 2 * HID * HID, LB = 2 * HID;   // last layer (index 2)
    const float* c1W1 = (const float*)d_in[5]  + LW;
    const float* c1b1 = (const float*)d_in[6]  + LB;
    const float* c1W2 = (const float*)d_in[7]  + LW;
    const float* c1b2 = (const float*)d_in[8]  + LB;
    const float* c3W1 = (const float*)d_in[9]  + LW;
    const float* c3b1 = (const float*)d_in[10] + LB;
    const float* c3W2 = (const float*)d_in[11] + LW;
    const float* c3b2 = (const float*)d_in[12] + LB;
    const float* c4W1 = (const float*)d_in[13] + LW;
    const float* c4b1 = (const float*)d_in[14] + LB;
    const float* c4W2 = (const float*)d_in[15] + LW;
    const float* c4b2 = (const float*)d_in[16] + LB;
    const float* postW = (const float*)d_in[17];
    const float* postB = (const float*)d_in[18];
    const float* roW   = (const float*)d_in[19];
    const float* roB   = (const float*)d_in[20];
    float* out = (float*)d_out;

    Scratch* s = nullptr;
    cudaGetSymbolAddress((void**)&s, g_s);

    const int GB = (NN + 63) / 64;           // gemm blocks (x)
    const int EB = (EE + 7) / 8;             // edge-warp blocks
    dim3 g1(GB, 1), g2(GB, 2);

    zero_init<<<4096, 256>>>(s);

    // h = x @ pre_W + pre_b
    {
        GArgs a{x, preW, preB, s->h};
        gemm64<FIN, false, false><<<g1, 128>>>(a, a, nullptr, NN);
    }

    // invariance branch (only layer 2 matters)
    scatter_ones<<<EB, 256>>>(row, col, s->h, s->Ai);
    {
        GArgs a{s->Ai, c3W1, c3b1, s->T1};
        gemm64<HID, true, true><<<g1, 128>>>(a, a, s->h, NN);
    }
    {
        GArgs a{s->T1, c3W2, c3b2, s->X1};
        gemm64<HID, false, true><<<g1, 128>>>(a, a, nullptr, NN);
    }

    // per-edge weights + radix histogram pass 0 (fused)
    ew_kernel<<<EB, 256>>>(row, col, s->X1, s->ew, s->hist);

    // exact top-k (k = 400000) radix select: 11 / 11 / 10 bits
    scan_kernel<<<1, 1024>>>(s->hist, &s->st, 2048, 11, 0);
    hist_kernel<<<1024, 256>>>(s->ew, s->hist, &s->st, 1);
    scan_kernel<<<1, 1024>>>(s->hist, &s->st, 2048, 11, 0);
    hist_kernel<<<1024, 256>>>(s->ew, s->hist, &s->st, 2);
    scan_kernel<<<1, 1024>>>(s->hist, &s->st, 1024, 10, 1);
    flag_kernel<<<2048, 256>>>(s->ew, s->flag, s->tie, &s->st);
    tie_resolve<<<1, 1024>>>(s->tie, s->flag, &s->st);

    // weighted scatters for both branches
    scatter_sel<<<EB, 256>>>(row, col, s->h, s->ew, s->flag, s->At, s->Ar);

    // dual-branch layer 1: T1 = relu((At+2h)@c1W1+b), T2 = relu((Ar+2h)@c4W1+b)
    {
        GArgs a{s->At, c1W1, c1b1, s->T1};
        GArgs b{s->Ar, c4W1, c4b1, s->T2};
        gemm64<HID, true, true><<<g2, 128>>>(a, b, s->h, NN);
    }
    // dual-branch layer 2: X1 = relu(T1@c1W2+b), X2 = relu(T2@c4W2+b)
    {
        GArgs a{s->T1, c1W2, c1b2, s->X1};
        GArgs b{s->T2, c4W2, c4b2, s->X2};
        gemm64<HID, false, true><<<g2, 128>>>(a, b, nullptr, NN);
    }

    // pool + head
    pool_kernel<<<(NN + NPB - 1) / NPB, HID>>>(s->X1, s->X2, batch, s->pool);
    head_kernel<<<NG, HID>>>(s->pool, postW, postB, roW, roB, out);
}

// round 3
// speedup vs baseline: 1.6365x; 1.6365x over previous
#include <cuda_runtime.h>

#define NN   50000
#define EE   800000
#define FIN  64
#define HID  128
#define NCLS 10
#define NG   128
#define KTOP 400000
#define MAX_TIES 4096

struct SelState {
    unsigned prefix;
    int kk;
    unsigned threshold;
    int needed;
    int tie_count;
};

struct __align__(16) Scratch {
    float h [(size_t)NN * HID];
    float Ai[(size_t)NN * HID];
    float At[(size_t)NN * HID];
    float Ar[(size_t)NN * HID];
    float T1[(size_t)NN * HID];
    float T2[(size_t)NN * HID];
    float X1[(size_t)NN * HID];
    float X2[(size_t)NN * HID];
    float ew[EE];
    unsigned char flag[EE];
    unsigned hist[2048];
    int tie[MAX_TIES];
    float pool[NG * HID];
    SelState st;
};
__device__ Scratch g_s;

// ---------------------------------------------------------------------------
// vector fp32 reduction to global (sm_90+)
// ---------------------------------------------------------------------------
__device__ __forceinline__ void red4(float* addr, float4 v) {
    asm volatile("red.global.add.v4.f32 [%0], {%1,%2,%3,%4};"
                 :: "l"(addr), "f"(v.x), "f"(v.y), "f"(v.z), "f"(v.w)
                 : "memory");
}

__device__ __forceinline__ unsigned fkey(float f) {
    unsigned u = __float_as_uint(f);
    return (u & 0x80000000u) ? ~u : (u | 0x80000000u);
}

// ---------------------------------------------------------------------------
// zero / init
// ---------------------------------------------------------------------------
__global__ void zero_init(Scratch* s) {
    size_t idx = (size_t)blockIdx.x * blockDim.x + threadIdx.x;
    size_t stride = (size_t)gridDim.x * blockDim.x;
    const size_t nf4 = (size_t)NN * HID / 4;
    float4 z = make_float4(0.f, 0.f, 0.f, 0.f);
    float4* ai = (float4*)s->Ai;
    float4* at = (float4*)s->At;
    float4* ar = (float4*)s->Ar;
    for (size_t i = idx; i < nf4; i += stride) {
        ai[i] = z; at[i] = z; ar[i] = z;
    }
    if (idx < (size_t)NG * HID / 4) ((float4*)s->pool)[idx] = z;
    if (idx < 2048) s->hist[idx] = 0;
    if (idx == 0) {
        s->st.prefix = 0;
        s->st.kk = KTOP;
        s->st.tie_count = 0;
    }
}

// ---------------------------------------------------------------------------
// GEMM: C[M x 128] = epilogue( (A + optional 2*H)[M x K] @ W[K x 128] + bias )
// Block tile 64 x 128, BK=16, 128 threads, 8x8 microtile split 2x2 quadrants.
// Double-buffered smem; dual-problem via blockIdx.y.
// ---------------------------------------------------------------------------
struct GArgs {
    const float* A;
    const float* W;
    const float* bias;
    float* C;
};

template<int K, bool ADD2H, bool RELU>
__global__ __launch_bounds__(128, 4)
void gemm64(GArgs g0, GArgs g1, const float* __restrict__ Hh, int M)
{
    __shared__ __align__(16) float As[2][16][64];
    __shared__ __align__(16) float Bs[2][16][128];

    GArgs g = (blockIdx.y == 1) ? g1 : g0;
    const float* __restrict__ A = g.A;
    const float* __restrict__ W = g.W;

    const int m0 = blockIdx.x * 64;
    const int t  = threadIdx.x;
    const int tx = t & 15;          // n quadrant selector (16)
    const int ty = t >> 4;          // m quadrant selector (8)

    // A-load mapping: 2 float4 per thread
    const int ar0 = t >> 2;         // 0..31 (l=0), +32 (l=1)
    const int akc = (t & 3) * 4;    // k sub-column within 16
    // B-load mapping: 4 float4 per thread
    const int bkr = t >> 5;         // 0..3 (+4*l)
    const int bc4 = (t & 31) * 4;   // n column *4

    float acc[8][8];
#pragma unroll
    for (int i = 0; i < 8; i++)
#pragma unroll
        for (int j = 0; j < 8; j++) acc[i][j] = 0.f;

    float4 av[2], bv[4];

    auto ldg_tiles = [&](int k0) {
#pragma unroll
        for (int l = 0; l < 2; l++) {
            int m = m0 + ar0 + l * 32;
            float4 v = make_float4(0.f, 0.f, 0.f, 0.f);
            if (m < M) {
                v = *(const float4*)&A[(size_t)m * K + k0 + akc];
                if (ADD2H) {
                    float4 hv = *(const float4*)&Hh[(size_t)m * K + k0 + akc];
                    v.x += 2.f * hv.x; v.y += 2.f * hv.y;
                    v.z += 2.f * hv.z; v.w += 2.f * hv.w;
                }
            }
            av[l] = v;
        }
#pragma unroll
        for (int l = 0; l < 4; l++)
            bv[l] = *(const float4*)&W[(size_t)(k0 + bkr + l * 4) * 128 + bc4];
    };

    auto sts_tiles = [&](int buf) {
#pragma unroll
        for (int l = 0; l < 2; l++) {
            int r = ar0 + l * 32;
            As[buf][akc + 0][r] = av[l].x;
            As[buf][akc + 1][r] = av[l].y;
            As[buf][akc + 2][r] = av[l].z;
            As[buf][akc + 3][r] = av[l].w;
        }
#pragma unroll
        for (int l = 0; l < 4; l++)
            *(float4*)&Bs[buf][bkr + l * 4][bc4] = bv[l];
    };

    auto compute = [&](int buf) {
#pragma unroll
        for (int kk = 0; kk < 16; kk++) {
            float4 a0 = *(const float4*)&As[buf][kk][ty * 4];
            float4 a1 = *(const float4*)&As[buf][kk][32 + ty * 4];
            float4 b0 = *(const float4*)&Bs[buf][kk][tx * 4];
            float4 b1 = *(const float4*)&Bs[buf][kk][64 + tx * 4];
            float aa[8] = {a0.x, a0.y, a0.z, a0.w, a1.x, a1.y, a1.z, a1.w};
            float bb[8] = {b0.x, b0.y, b0.z, b0.w, b1.x, b1.y, b1.z, b1.w};
#pragma unroll
            for (int i = 0; i < 8; i++)
#pragma unroll
                for (int j = 0; j < 8; j++)
                    acc[i][j] += aa[i] * bb[j];
        }
    };

    ldg_tiles(0);
    sts_tiles(0);
    __syncthreads();
    int buf = 0;
    for (int k0 = 16; k0 < K; k0 += 16) {
        ldg_tiles(k0);
        compute(buf);
        sts_tiles(buf ^ 1);
        __syncthreads();
        buf ^= 1;
    }
    compute(buf);

    const float4 bias0 = *(const float4*)&g.bias[tx * 4];
    const float4 bias1 = *(const float4*)&g.bias[64 + tx * 4];
#pragma unroll
    for (int gi = 0; gi < 2; gi++) {
#pragma unroll
        for (int i = 0; i < 4; i++) {
            int m = m0 + gi * 32 + ty * 4 + i;
            if (m >= M) continue;
            int ri = gi * 4 + i;
            float4 v0, v1;
            v0.x = acc[ri][0] + bias0.x; v0.y = acc[ri][1] + bias0.y;
            v0.z = acc[ri][2] + bias0.z; v0.w = acc[ri][3] + bias0.w;
            v1.x = acc[ri][4] + bias1.x; v1.y = acc[ri][5] + bias1.y;
            v1.z = acc[ri][6] + bias1.z; v1.w = acc[ri][7] + bias1.w;
            if (RELU) {
                v0.x = fmaxf(v0.x, 0.f); v0.y = fmaxf(v0.y, 0.f);
                v0.z = fmaxf(v0.z, 0.f); v0.w = fmaxf(v0.w, 0.f);
                v1.x = fmaxf(v1.x, 0.f); v1.y = fmaxf(v1.y, 0.f);
                v1.z = fmaxf(v1.z, 0.f); v1.w = fmaxf(v1.w, 0.f);
            }
            *(float4*)&g.C[(size_t)m * 128 + tx * 4] = v0;
            *(float4*)&g.C[(size_t)m * 128 + 64 + tx * 4] = v1;
        }
    }
}

// ---------------------------------------------------------------------------
// scatter (weight 1): agg[col] += h[row]
// ---------------------------------------------------------------------------
__global__ void scatter_ones(const int* __restrict__ row, const int* __restrict__ col,
                             const float* __restrict__ h, float* __restrict__ out)
{
    int e = blockIdx.x * 8 + (threadIdx.x >> 5);
    if (e >= EE) return;
    int lane = threadIdx.x & 31;
    int r = __ldg(&row[e]);
    int c = __ldg(&col[e]);
    float4 v = *(const float4*)(h + (size_t)r * HID + lane * 4);
    red4(out + (size_t)c * HID + lane * 4, v);
}

// ---------------------------------------------------------------------------
// per-edge dot: ew[e] = <X[row], X[col]>   (pure — no global atomics)
// ---------------------------------------------------------------------------
__global__ void ew_kernel(const int* __restrict__ row, const int* __restrict__ col,
                          const float* __restrict__ X, float* __restrict__ ew)
{
    int e = blockIdx.x * 8 + (threadIdx.x >> 5);
    if (e >= EE) return;
    int lane = threadIdx.x & 31;
    int r = __ldg(&row[e]);
    int c = __ldg(&col[e]);
    float4 a = *(const float4*)(X + (size_t)r * HID + lane * 4);
    float4 b = *(const float4*)(X + (size_t)c * HID + lane * 4);
    float s = a.x * b.x + a.y * b.y + a.z * b.z + a.w * b.w;
#pragma unroll
    for (int off = 16; off >= 1; off >>= 1)
        s += __shfl_xor_sync(0xFFFFFFFFu, s, off);
    if (lane == 0) ew[e] = s;
}

// ---------------------------------------------------------------------------
// radix-select histogram passes (shared-memory privatized)
// ---------------------------------------------------------------------------
__global__ void hist_kernel(const float* __restrict__ ew, unsigned* __restrict__ hist,
                            const SelState* __restrict__ st, int pass)
{
    __shared__ unsigned sh[2048];
    for (int i = threadIdx.x; i < 2048; i += blockDim.x) sh[i] = 0;
    __syncthreads();
    unsigned pref = st->prefix;
    int stride = gridDim.x * blockDim.x;
    for (int e = blockIdx.x * blockDim.x + threadIdx.x; e < EE; e += stride) {
        unsigned u = fkey(ew[e]);
        if (pass == 0) {
            atomicAdd(&sh[u >> 21], 1u);
        } else if (pass == 1) {
            if ((u >> 21) == pref) atomicAdd(&sh[(u >> 10) & 2047u], 1u);
        } else {
            if ((u >> 10) == pref) atomicAdd(&sh[u & 1023u], 1u);
        }
    }
    __syncthreads();
    for (int i = threadIdx.x; i < 2048; i += blockDim.x)
        if (sh[i]) atomicAdd(&hist[i], sh[i]);
}

// ---------------------------------------------------------------------------
// suffix-scan of histogram; pick bucket, update state; zeroes hist for next use
// ---------------------------------------------------------------------------
__global__ void scan_kernel(unsigned* __restrict__ hist, SelState* __restrict__ st,
                            int nbins, int bits, int last)
{
    __shared__ unsigned a[2048], b[2048];
    __shared__ int bstar;
    int tid = threadIdx.x;
    for (int i = tid; i < 2048; i += blockDim.x) {
        a[i] = (i < nbins) ? hist[i] : 0u;
        hist[i] = 0u;
    }
    __syncthreads();
    unsigned* src = a;
    unsigned* dst = b;
    for (int off = 1; off < nbins; off <<= 1) {
        for (int i = tid; i < nbins; i += blockDim.x)
            dst[i] = src[i] + ((i + off < nbins) ? src[i + off] : 0u);
        __syncthreads();
        unsigned* t = src; src = dst; dst = t;
    }
    int kk = st->kk;
    for (int i = tid; i < nbins; i += blockDim.x) {
        unsigned Si = src[i];
        unsigned Sn = (i + 1 < nbins) ? src[i + 1] : 0u;
        if (Si >= (unsigned)kk && Sn < (unsigned)kk) bstar = i;
    }
    __syncthreads();
    if (tid == 0) {
        int bs = bstar;
        unsigned greater = (bs + 1 < nbins) ? src[bs + 1] : 0u;
        st->kk = kk - (int)greater;
        st->prefix = (st->prefix << bits) | (unsigned)bs;
        if (last) {
            st->threshold = st->prefix;
            st->needed = st->kk;
        }
    }
}

// ---------------------------------------------------------------------------
// flag edges strictly above threshold; collect ties
// ---------------------------------------------------------------------------
__global__ void flag_kernel(const float* __restrict__ ew, unsigned char* __restrict__ flag,
                            int* __restrict__ tie, SelState* __restrict__ st)
{
    unsigned T = st->threshold;
    int stride = gridDim.x * blockDim.x;
    for (int e = blockIdx.x * blockDim.x + threadIdx.x; e < EE; e += stride) {
        unsigned u = fkey(ew[e]);
        flag[e] = (u > T) ? (unsigned char)1 : (unsigned char)0;
        if (u == T) {
            int p = atomicAdd(&st->tie_count, 1);
            if (p < MAX_TIES) tie[p] = e;
        }
    }
}

// ---------------------------------------------------------------------------
// pick `needed` lowest-index ties (matches jax.lax.top_k stability)
// ---------------------------------------------------------------------------
__global__ void tie_resolve(int* __restrict__ tie, unsigned char* __restrict__ flag,
                            const SelState* __restrict__ st)
{
    __shared__ int s[MAX_TIES];
    int C = st->tie_count;
    if (C > MAX_TIES) C = MAX_TIES;
    int nd = st->needed;
    int tid = threadIdx.x;
    if (C <= nd) {
        for (int i = tid; i < C; i += blockDim.x) flag[tie[i]] = 1;
        return;
    }
    for (int i = tid; i < C; i += blockDim.x) s[i] = tie[i];
    __syncthreads();
    for (int ph = 0; ph < C; ph++) {
        for (int i = 2 * tid + (ph & 1); i + 1 < C; i += 2 * blockDim.x) {
            if (s[i] > s[i + 1]) { int t = s[i]; s[i] = s[i + 1]; s[i + 1] = t; }
        }
        __syncthreads();
    }
    for (int i = tid; i < nd; i += blockDim.x) flag[s[i]] = 1;
}

// ---------------------------------------------------------------------------
// weighted scatter into top / remaining aggregates
// ---------------------------------------------------------------------------
__global__ void scatter_sel(const int* __restrict__ row, const int* __restrict__ col,
                            const float* __restrict__ h, const float* __restrict__ ew,
                            const unsigned char* __restrict__ flag,
                            float* __restrict__ At, float* __restrict__ Ar)
{
    int e = blockIdx.x * 8 + (threadIdx.x >> 5);
    if (e >= EE) return;
    int lane = threadIdx.x & 31;
    int r = __ldg(&row[e]);
    int c = __ldg(&col[e]);
    float w = __ldg(&ew[e]);
    float4 v = *(const float4*)(h + (size_t)r * HID + lane * 4);
    v.x *= w; v.y *= w; v.z *= w; v.w *= w;
    float* dst = flag[e] ? At : Ar;
    red4(dst + (size_t)c * HID + lane * 4, v);
}

// ---------------------------------------------------------------------------
// pooling: pooled[batch[n]] += x1[n] + x2[n]   (batch sorted -> run flush)
// ---------------------------------------------------------------------------
#define NPB 128
__global__ void pool_kernel(const float* __restrict__ x1, const float* __restrict__ x2,
                            const int* __restrict__ batch, float* __restrict__ pooled)
{
    int f = threadIdx.x;
    int n0 = blockIdx.x * NPB;
    if (n0 >= NN) return;
    int n1 = n0 + NPB;
    if (n1 > NN) n1 = NN;
    int cur = batch[n0];
    float acc = 0.f;
    for (int n = n0; n < n1; n++) {
        int b = batch[n];
        if (b != cur) {
            atomicAdd(&pooled[cur * HID + f], acc);
            acc = 0.f;
            cur = b;
        }
        acc += x1[(size_t)n * HID + f] + x2[(size_t)n * HID + f];
    }
    atomicAdd(&pooled[cur * HID + f], acc);
}

// ---------------------------------------------------------------------------
// head: p = relu(pooled@post_W+post_b); logits = p@ro_W+ro_b; log_softmax
// ---------------------------------------------------------------------------
__global__ void head_kernel(const float* __restrict__ pool,
                            const float* __restrict__ pW, const float* __restrict__ pb,
                            const float* __restrict__ rW, const float* __restrict__ rb,
                            float* __restrict__ out)
{
    __shared__ float rowv[HID], p[HID], lg[NCLS];
    int g = blockIdx.x, t = threadIdx.x;
    rowv[t] = pool[g * HID + t];
    __syncthreads();
    float s = pb[t];
#pragma unroll 8
    for (int k = 0; k < HID; k++) s += rowv[k] * pW[k * HID + t];
    p[t] = fmaxf(s, 0.f);
    __syncthreads();
    if (t < NCLS) {
        float s2 = rb[t];
#pragma unroll 8
        for (int k = 0; k < HID; k++) s2 += p[k] * rW[k * NCLS + t];
        lg[t] = s2;
    }
    __syncthreads();
    if (t == 0) {
        float mx = lg[0];
        for (int j = 1; j < NCLS; j++) mx = fmaxf(mx, lg[j]);
        float se = 0.f;
        for (int j = 0; j < NCLS; j++) se += expf(lg[j] - mx);
        float l = logf(se) + mx;
        for (int j = 0; j < NCLS; j++) out[g * NCLS + j] = lg[j] - l;
    }
}

// ---------------------------------------------------------------------------
// launch
// ---------------------------------------------------------------------------
extern "C" void kernel_launch(void* const* d_in, const int* in_sizes, int n_in,
                              void* d_out, int out_size)
{
    (void)in_sizes; (void)n_in; (void)out_size;
    const float* x     = (const float*)d_in[0];
    const int*   ei    = (const int*)d_in[1];
    const int*   row   = ei;
    const int*   col   = ei + EE;
    const int*   batch = (const int*)d_in[2];
    const float* preW  = (const float*)d_in[3];
    const float* preB  = (const float*)d_in[4];
    const int LW = 2 * HID * HID, LB = 2 * HID;   // last layer (index 2)
    const float* c1W1 = (const float*)d_in[5]  + LW;
    const float* c1b1 = (const float*)d_in[6]  + LB;
    const float* c1W2 = (const float*)d_in[7]  + LW;
    const float* c1b2 = (const float*)d_in[8]  + LB;
    const float* c3W1 = (const float*)d_in[9]  + LW;
    const float* c3b1 = (const float*)d_in[10] + LB;
    const float* c3W2 = (const float*)d_in[11] + LW;
    const float* c3b2 = (const float*)d_in[12] + LB;
    const float* c4W1 = (const float*)d_in[13] + LW;
    const float* c4b1 = (const float*)d_in[14] + LB;
    const float* c4W2 = (const float*)d_in[15] + LW;
    const float* c4b2 = (const float*)d_in[16] + LB;
    const float* postW = (const float*)d_in[17];
    const float* postB = (const float*)d_in[18];
    const float* roW   = (const float*)d_in[19];
    const float* roB   = (const float*)d_in[20];
    float* out = (float*)d_out;

    Scratch* s = nullptr;
    cudaGetSymbolAddress((void**)&s, g_s);

    const int GB = (NN + 63) / 64;           // gemm blocks (x)
    const int EB = (EE + 7) / 8;             // edge-warp blocks
    dim3 g1(GB, 1), g2(GB, 2);

    zero_init<<<4096, 256>>>(s);

    // h = x @ pre_W + pre_b
    {
        GArgs a{x, preW, preB, s->h};
        gemm64<FIN, false, false><<<g1, 128>>>(a, a, nullptr, NN);
    }

    // invariance branch (only layer 2 matters)
    scatter_ones<<<EB, 256>>>(row, col, s->h, s->Ai);
    {
        GArgs a{s->Ai, c3W1, c3b1, s->T1};
        gemm64<HID, true, true><<<g1, 128>>>(a, a, s->h, NN);
    }
    {
        GArgs a{s->T1, c3W2, c3b2, s->X1};
        gemm64<HID, false, true><<<g1, 128>>>(a, a, nullptr, NN);
    }

    // per-edge weights
    ew_kernel<<<EB, 256>>>(row, col, s->X1, s->ew);

    // exact top-k (k = 400000) radix select: 11 / 11 / 10 bits
    hist_kernel<<<1024, 256>>>(s->ew, s->hist, &s->st, 0);
    scan_kernel<<<1, 1024>>>(s->hist, &s->st, 2048, 11, 0);
    hist_kernel<<<1024, 256>>>(s->ew, s->hist, &s->st, 1);
    scan_kernel<<<1, 1024>>>(s->hist, &s->st, 2048, 11, 0);
    hist_kernel<<<1024, 256>>>(s->ew, s->hist, &s->st, 2);
    scan_kernel<<<1, 1024>>>(s->hist, &s->st, 1024, 10, 1);
    flag_kernel<<<2048, 256>>>(s->ew, s->flag, s->tie, &s->st);
    tie_resolve<<<1, 1024>>>(s->tie, s->flag, &s->st);

    // weighted scatters for both branches
    scatter_sel<<<EB, 256>>>(row, col, s->h, s->ew, s->flag, s->At, s->Ar);

    // dual-branch layer 1: T1 = relu((At+2h)@c1W1+b), T2 = relu((Ar+2h)@c4W1+b)
    {
        GArgs a{s->At, c1W1, c1b1, s->T1};
        GArgs b{s->Ar, c4W1, c4b1, s->T2};
        gemm64<HID, true, true><<<g2, 128>>>(a, b, s->h, NN);
    }
    // dual-branch layer 2: X1 = relu(T1@c1W2+b), X2 = relu(T2@c4W2+b)
    {
        GArgs a{s->T1, c1W2, c1b2, s->X1};
        GArgs b{s->T2, c4W2, c4b2, s->X2};
        gemm64<HID, false, true><<<g2, 128>>>(a, b, nullptr, NN);
    }

    // pool + head
    pool_kernel<<<(NN + NPB - 1) / NPB, HID>>>(s->X1, s->X2, batch, s->pool);
    head_kernel<<<NG, HID>>>(s->pool, postW, postB, roW, roB, out);
}

// round 4
// speedup vs baseline: 1.6973x; 1.0372x over previous
#include <cuda_runtime.h>

#define NN   50000
#define EE   800000
#define FIN  64
#define HID  128
#define NCLS 10
#define NG   128
#define KTOP 400000
#define MAX_TIES 4096

struct SelState {
    unsigned prefix;
    int kk;
    unsigned threshold;
    int needed;
    int tie_count;
};

struct __align__(16) Scratch {
    float h [(size_t)NN * HID];
    float Ai[(size_t)NN * HID];
    float At[(size_t)NN * HID];
    float Ar[(size_t)NN * HID];
    float T1[(size_t)NN * HID];
    float T2[(size_t)NN * HID];
    float X1[(size_t)NN * HID];
    float X2[(size_t)NN * HID];
    float ew[EE];
    unsigned char flag[EE];
    unsigned hist[2048];
    int tie[MAX_TIES];
    float pool[NG * HID];
    SelState st;
};
__device__ Scratch g_s;

// ---------------------------------------------------------------------------
// vector fp32 reduction to global (sm_90+)
// ---------------------------------------------------------------------------
__device__ __forceinline__ void red4(float* addr, float4 v) {
    asm volatile("red.global.add.v4.f32 [%0], {%1,%2,%3,%4};"
                 :: "l"(addr), "f"(v.x), "f"(v.y), "f"(v.z), "f"(v.w)
                 : "memory");
}

__device__ __forceinline__ unsigned fkey(float f) {
    unsigned u = __float_as_uint(f);
    return (u & 0x80000000u) ? ~u : (u | 0x80000000u);
}

// packed fp32x2 FMA (Blackwell): d = a * b + d, lanewise on 2 packed floats
__device__ __forceinline__ void ffma2(unsigned long long& d,
                                      unsigned long long a,
                                      unsigned long long b) {
    asm("fma.rn.f32x2 %0, %1, %2, %0;" : "+l"(d) : "l"(a), "l"(b));
}

// duplicate one float into both halves of a b64
__device__ __forceinline__ unsigned long long dup2(float a) {
    unsigned long long r;
    asm("mov.b64 %0, {%1, %1};" : "=l"(r) : "r"(__float_as_uint(a)));
    return r;
}

__device__ __forceinline__ float2 unpk(unsigned long long v) {
    float2 r;
    asm("mov.b64 {%0, %1}, %2;" : "=f"(r.x), "=f"(r.y) : "l"(v));
    return r;
}

// ---------------------------------------------------------------------------
// zero / init
// ---------------------------------------------------------------------------
__global__ void zero_init(Scratch* s) {
    size_t idx = (size_t)blockIdx.x * blockDim.x + threadIdx.x;
    size_t stride = (size_t)gridDim.x * blockDim.x;
    const size_t nf4 = (size_t)NN * HID / 4;
    float4 z = make_float4(0.f, 0.f, 0.f, 0.f);
    float4* ai = (float4*)s->Ai;
    float4* at = (float4*)s->At;
    float4* ar = (float4*)s->Ar;
    for (size_t i = idx; i < nf4; i += stride) {
        ai[i] = z; at[i] = z; ar[i] = z;
    }
    if (idx < (size_t)NG * HID / 4) ((float4*)s->pool)[idx] = z;
    if (idx < 2048) s->hist[idx] = 0;
    if (idx == 0) {
        s->st.prefix = 0;
        s->st.kk = KTOP;
        s->st.tie_count = 0;
    }
}

// ---------------------------------------------------------------------------
// GEMM: C[M x 128] = epilogue( (A + optional 2*H)[M x K] @ W[K x 128] + bias )
// Block tile 64 x 128, BK=16, 128 threads, 8x8 microtile (2x2 quadrants).
// Inner product uses packed fma.rn.f32x2 (2 FMA per issue slot).
// ---------------------------------------------------------------------------
struct GArgs {
    const float* A;
    const float* W;
    const float* bias;
    float* C;
};

template<int K, bool ADD2H, bool RELU>
__global__ __launch_bounds__(128, 4)
void gemm64(GArgs g0, GArgs g1, const float* __restrict__ Hh, int M)
{
    __shared__ __align__(16) float As[2][16][64];
    __shared__ __align__(16) float Bs[2][16][128];

    GArgs g = (blockIdx.y == 1) ? g1 : g0;
    const float* __restrict__ A = g.A;
    const float* __restrict__ W = g.W;

    const int m0 = blockIdx.x * 64;
    const int t  = threadIdx.x;
    const int tx = t & 15;          // n quadrant selector (16)
    const int ty = t >> 4;          // m quadrant selector (8)

    const int ar0 = t >> 2;         // A-load row 0..31 (l=0), +32 (l=1)
    const int akc = (t & 3) * 4;    // k sub-column within 16
    const int bkr = t >> 5;         // B-load k row 0..3 (+4*l)
    const int bc4 = (t & 31) * 4;   // B-load n column *4

    // packed accumulators: acc2[i][j] holds columns (pair j) for row i
    unsigned long long acc2[8][4];
#pragma unroll
    for (int i = 0; i < 8; i++)
#pragma unroll
        for (int j = 0; j < 4; j++) acc2[i][j] = 0ull;

    float4 av[2], bv[4];

    auto ldg_tiles = [&](int k0) {
#pragma unroll
        for (int l = 0; l < 2; l++) {
            int m = m0 + ar0 + l * 32;
            float4 v = make_float4(0.f, 0.f, 0.f, 0.f);
            if (m < M) {
                v = *(const float4*)&A[(size_t)m * K + k0 + akc];
                if (ADD2H) {
                    float4 hv = *(const float4*)&Hh[(size_t)m * K + k0 + akc];
                    v.x += 2.f * hv.x; v.y += 2.f * hv.y;
                    v.z += 2.f * hv.z; v.w += 2.f * hv.w;
                }
            }
            av[l] = v;
        }
#pragma unroll
        for (int l = 0; l < 4; l++)
            bv[l] = *(const float4*)&W[(size_t)(k0 + bkr + l * 4) * 128 + bc4];
    };

    auto sts_tiles = [&](int buf) {
#pragma unroll
        for (int l = 0; l < 2; l++) {
            int r = ar0 + l * 32;
            As[buf][akc + 0][r] = av[l].x;
            As[buf][akc + 1][r] = av[l].y;
            As[buf][akc + 2][r] = av[l].z;
            As[buf][akc + 3][r] = av[l].w;
        }
#pragma unroll
        for (int l = 0; l < 4; l++)
            *(float4*)&Bs[buf][bkr + l * 4][bc4] = bv[l];
    };

    auto compute = [&](int buf) {
#pragma unroll
        for (int kk = 0; kk < 16; kk++) {
            float4 a0 = *(const float4*)&As[buf][kk][ty * 4];
            float4 a1 = *(const float4*)&As[buf][kk][32 + ty * 4];
            // B pairs: 2 consecutive columns per u64 (lo = even col, hi = odd)
            ulonglong2 p0 = *(const ulonglong2*)&Bs[buf][kk][tx * 4];
            ulonglong2 p1 = *(const ulonglong2*)&Bs[buf][kk][64 + tx * 4];
            unsigned long long bb[4] = {p0.x, p0.y, p1.x, p1.y};
            float aa[8] = {a0.x, a0.y, a0.z, a0.w, a1.x, a1.y, a1.z, a1.w};
#pragma unroll
            for (int i = 0; i < 8; i++) {
                unsigned long long ad = dup2(aa[i]);
                ffma2(acc2[i][0], ad, bb[0]);
                ffma2(acc2[i][1], ad, bb[1]);
                ffma2(acc2[i][2], ad, bb[2]);
                ffma2(acc2[i][3], ad, bb[3]);
            }
        }
    };

    ldg_tiles(0);
    sts_tiles(0);
    __syncthreads();
    int buf = 0;
    for (int k0 = 16; k0 < K; k0 += 16) {
        ldg_tiles(k0);
        compute(buf);
        sts_tiles(buf ^ 1);
        __syncthreads();
        buf ^= 1;
    }
    compute(buf);

    const float4 bias0 = *(const float4*)&g.bias[tx * 4];
    const float4 bias1 = *(const float4*)&g.bias[64 + tx * 4];
#pragma unroll
    for (int gi = 0; gi < 2; gi++) {
#pragma unroll
        for (int i = 0; i < 4; i++) {
            int m = m0 + gi * 32 + ty * 4 + i;
            if (m >= M) continue;
            int ri = gi * 4 + i;
            float2 c0 = unpk(acc2[ri][0]);
            float2 c1 = unpk(acc2[ri][1]);
            float2 c2 = unpk(acc2[ri][2]);
            float2 c3 = unpk(acc2[ri][3]);
            float4 v0, v1;
            v0.x = c0.x + bias0.x; v0.y = c0.y + bias0.y;
            v0.z = c1.x + bias0.z; v0.w = c1.y + bias0.w;
            v1.x = c2.x + bias1.x; v1.y = c2.y + bias1.y;
            v1.z = c3.x + bias1.z; v1.w = c3.y + bias1.w;
            if (RELU) {
                v0.x = fmaxf(v0.x, 0.f); v0.y = fmaxf(v0.y, 0.f);
                v0.z = fmaxf(v0.z, 0.f); v0.w = fmaxf(v0.w, 0.f);
                v1.x = fmaxf(v1.x, 0.f); v1.y = fmaxf(v1.y, 0.f);
                v1.z = fmaxf(v1.z, 0.f); v1.w = fmaxf(v1.w, 0.f);
            }
            *(float4*)&g.C[(size_t)m * 128 + tx * 4] = v0;
            *(float4*)&g.C[(size_t)m * 128 + 64 + tx * 4] = v1;
        }
    }
}

// ---------------------------------------------------------------------------
// scatter (weight 1): agg[col] += h[row]
// ---------------------------------------------------------------------------
__global__ void scatter_ones(const int* __restrict__ row, const int* __restrict__ col,
                             const float* __restrict__ h, float* __restrict__ out)
{
    int e = blockIdx.x * 8 + (threadIdx.x >> 5);
    if (e >= EE) return;
    int lane = threadIdx.x & 31;
    int r = __ldg(&row[e]);
    int c = __ldg(&col[e]);
    float4 v = *(const float4*)(h + (size_t)r * HID + lane * 4);
    red4(out + (size_t)c * HID + lane * 4, v);
}

// ---------------------------------------------------------------------------
// per-edge dot: ew[e] = <X[row], X[col]>   (pure — no global atomics)
// ---------------------------------------------------------------------------
__global__ void ew_kernel(const int* __restrict__ row, const int* __restrict__ col,
                          const float* __restrict__ X, float* __restrict__ ew)
{
    int e = blockIdx.x * 8 + (threadIdx.x >> 5);
    if (e >= EE) return;
    int lane = threadIdx.x & 31;
    int r = __ldg(&row[e]);
    int c = __ldg(&col[e]);
    float4 a = *(const float4*)(X + (size_t)r * HID + lane * 4);
    float4 b = *(const float4*)(X + (size_t)c * HID + lane * 4);
    float s = a.x * b.x + a.y * b.y + a.z * b.z + a.w * b.w;
#pragma unroll
    for (int off = 16; off >= 1; off >>= 1)
        s += __shfl_xor_sync(0xFFFFFFFFu, s, off);
    if (lane == 0) ew[e] = s;
}

// ---------------------------------------------------------------------------
// radix-select histogram passes (shared-memory privatized)
// ---------------------------------------------------------------------------
__global__ void hist_kernel(const float* __restrict__ ew, unsigned* __restrict__ hist,
                            const SelState* __restrict__ st, int pass)
{
    __shared__ unsigned sh[2048];
    for (int i = threadIdx.x; i < 2048; i += blockDim.x) sh[i] = 0;
    __syncthreads();
    unsigned pref = st->prefix;
    int stride = gridDim.x * blockDim.x;
    for (int e = blockIdx.x * blockDim.x + threadIdx.x; e < EE; e += stride) {
        unsigned u = fkey(ew[e]);
        if (pass == 0) {
            atomicAdd(&sh[u >> 21], 1u);
        } else if (pass == 1) {
            if ((u >> 21) == pref) atomicAdd(&sh[(u >> 10) & 2047u], 1u);
        } else {
            if ((u >> 10) == pref) atomicAdd(&sh[u & 1023u], 1u);
        }
    }
    __syncthreads();
    for (int i = threadIdx.x; i < 2048; i += blockDim.x)
        if (sh[i]) atomicAdd(&hist[i], sh[i]);
}

// ---------------------------------------------------------------------------
// suffix-scan of histogram; pick bucket, update state; zeroes hist for next use
// ---------------------------------------------------------------------------
__global__ void scan_kernel(unsigned* __restrict__ hist, SelState* __restrict__ st,
                            int nbins, int bits, int last)
{
    __shared__ unsigned a[2048], b[2048];
    __shared__ int bstar;
    int tid = threadIdx.x;
    for (int i = tid; i < 2048; i += blockDim.x) {
        a[i] = (i < nbins) ? hist[i] : 0u;
        hist[i] = 0u;
    }
    __syncthreads();
    unsigned* src = a;
    unsigned* dst = b;
    for (int off = 1; off < nbins; off <<= 1) {
        for (int i = tid; i < nbins; i += blockDim.x)
            dst[i] = src[i] + ((i + off < nbins) ? src[i + off] : 0u);
        __syncthreads();
        unsigned* t = src; src = dst; dst = t;
    }
    int kk = st->kk;
    for (int i = tid; i < nbins; i += blockDim.x) {
        unsigned Si = src[i];
        unsigned Sn = (i + 1 < nbins) ? src[i + 1] : 0u;
        if (Si >= (unsigned)kk && Sn < (unsigned)kk) bstar = i;
    }
    __syncthreads();
    if (tid == 0) {
        int bs = bstar;
        unsigned greater = (bs + 1 < nbins) ? src[bs + 1] : 0u;
        st->kk = kk - (int)greater;
        st->prefix = (st->prefix << bits) | (unsigned)bs;
        if (last) {
            st->threshold = st->prefix;
            st->needed = st->kk;
        }
    }
}

// ---------------------------------------------------------------------------
// flag edges strictly above threshold; collect ties
// ---------------------------------------------------------------------------
__global__ void flag_kernel(const float* __restrict__ ew, unsigned char* __restrict__ flag,
                            int* __restrict__ tie, SelState* __restrict__ st)
{
    unsigned T = st->threshold;
    int stride = gridDim.x * blockDim.x;
    for (int e = blockIdx.x * blockDim.x + threadIdx.x; e < EE; e += stride) {
        unsigned u = fkey(ew[e]);
        flag[e] = (u > T) ? (unsigned char)1 : (unsigned char)0;
        if (u == T) {
            int p = atomicAdd(&st->tie_count, 1);
            if (p < MAX_TIES) tie[p] = e;
        }
    }
}

// ---------------------------------------------------------------------------
// pick `needed` lowest-index ties (matches jax.lax.top_k stability)
// ---------------------------------------------------------------------------
__global__ void tie_resolve(int* __restrict__ tie, unsigned char* __restrict__ flag,
                            const SelState* __restrict__ st)
{
    __shared__ int s[MAX_TIES];
    int C = st->tie_count;
    if (C > MAX_TIES) C = MAX_TIES;
    int nd = st->needed;
    int tid = threadIdx.x;
    if (C <= nd) {
        for (int i = tid; i < C; i += blockDim.x) flag[tie[i]] = 1;
        return;
    }
    for (int i = tid; i < C; i += blockDim.x) s[i] = tie[i];
    __syncthreads();
    for (int ph = 0; ph < C; ph++) {
        for (int i = 2 * tid + (ph & 1); i + 1 < C; i += 2 * blockDim.x) {
            if (s[i] > s[i + 1]) { int t = s[i]; s[i] = s[i + 1]; s[i + 1] = t; }
        }
        __syncthreads();
    }
    for (int i = tid; i < nd; i += blockDim.x) flag[s[i]] = 1;
}

// ---------------------------------------------------------------------------
// weighted scatter into top / remaining aggregates
// ---------------------------------------------------------------------------
__global__ void scatter_sel(const int* __restrict__ row, const int* __restrict__ col,
                            const float* __restrict__ h, const float* __restrict__ ew,
                            const unsigned char* __restrict__ flag,
                            float* __restrict__ At, float* __restrict__ Ar)
{
    int e = blockIdx.x * 8 + (threadIdx.x >> 5);
    if (e >= EE) return;
    int lane = threadIdx.x & 31;
    int r = __ldg(&row[e]);
    int c = __ldg(&col[e]);
    float w = __ldg(&ew[e]);
    float4 v = *(const float4*)(h + (size_t)r * HID + lane * 4);
    v.x *= w; v.y *= w; v.z *= w; v.w *= w;
    float* dst = flag[e] ? At : Ar;
    red4(dst + (size_t)c * HID + lane * 4, v);
}

// ---------------------------------------------------------------------------
// pooling: pooled[batch[n]] += x1[n] + x2[n]   (batch sorted -> run flush)
// ---------------------------------------------------------------------------
#define NPB 128
__global__ void pool_kernel(const float* __restrict__ x1, const float* __restrict__ x2,
                            const int* __restrict__ batch, float* __restrict__ pooled)
{
    int f = threadIdx.x;
    int n0 = blockIdx.x * NPB;
    if (n0 >= NN) return;
    int n1 = n0 + NPB;
    if (n1 > NN) n1 = NN;
    int cur = batch[n0];
    float acc = 0.f;
    for (int n = n0; n < n1; n++) {
        int b = batch[n];
        if (b != cur) {
            atomicAdd(&pooled[cur * HID + f], acc);
            acc = 0.f;
            cur = b;
        }
        acc += x1[(size_t)n * HID + f] + x2[(size_t)n * HID + f];
    }
    atomicAdd(&pooled[cur * HID + f], acc);
}

// ---------------------------------------------------------------------------
// head: p = relu(pooled@post_W+post_b); logits = p@ro_W+ro_b; log_softmax
// ---------------------------------------------------------------------------
__global__ void head_kernel(const float* __restrict__ pool,
                            const float* __restrict__ pW, const float* __restrict__ pb,
                            const float* __restrict__ rW, const float* __restrict__ rb,
                            float* __restrict__ out)
{
    __shared__ float rowv[HID], p[HID], lg[NCLS];
    int g = blockIdx.x, t = threadIdx.x;
    rowv[t] = pool[g * HID + t];
    __syncthreads();
    float s = pb[t];
#pragma unroll 8
    for (int k = 0; k < HID; k++) s += rowv[k] * pW[k * HID + t];
    p[t] = fmaxf(s, 0.f);
    __syncthreads();
    if (t < NCLS) {
        float s2 = rb[t];
#pragma unroll 8
        for (int k = 0; k < HID; k++) s2 += p[k] * rW[k * NCLS + t];
        lg[t] = s2;
    }
    __syncthreads();
    if (t == 0) {
        float mx = lg[0];
        for (int j = 1; j < NCLS; j++) mx = fmaxf(mx, lg[j]);
        float se = 0.f;
        for (int j = 0; j < NCLS; j++) se += expf(lg[j] - mx);
        float l = logf(se) + mx;
        for (int j = 0; j < NCLS; j++) out[g * NCLS + j] = lg[j] - l;
    }
}

// ---------------------------------------------------------------------------
// launch
// ---------------------------------------------------------------------------
extern "C" void kernel_launch(void* const* d_in, const int* in_sizes, int n_in,
                              void* d_out, int out_size)
{
    (void)in_sizes; (void)n_in; (void)out_size;
    const float* x     = (const float*)d_in[0];
    const int*   ei    = (const int*)d_in[1];
    const int*   row   = ei;
    const int*   col   = ei + EE;
    const int*   batch = (const int*)d_in[2];
    const float* preW  = (const float*)d_in[3];
    const float* preB  = (const float*)d_in[4];
    const int LW = 2 * HID * HID, LB = 2 * HID;   // last layer (index 2)
    const float* c1W1 = (const float*)d_in[5]  + LW;
    const float* c1b1 = (const float*)d_in[6]  + LB;
    const float* c1W2 = (const float*)d_in[7]  + LW;
    const float* c1b2 = (const float*)d_in[8]  + LB;
    const float* c3W1 = (const float*)d_in[9]  + LW;
    const float* c3b1 = (const float*)d_in[10] + LB;
    const float* c3W2 = (const float*)d_in[11] + LW;
    const float* c3b2 = (const float*)d_in[12] + LB;
    const float* c4W1 = (const float*)d_in[13] + LW;
    const float* c4b1 = (const float*)d_in[14] + LB;
    const float* c4W2 = (const float*)d_in[15] + LW;
    const float* c4b2 = (const float*)d_in[16] + LB;
    const float* postW = (const float*)d_in[17];
    const float* postB = (const float*)d_in[18];
    const float* roW   = (const float*)d_in[19];
    const float* roB   = (const float*)d_in[20];
    float* out = (float*)d_out;

    Scratch* s = nullptr;
    cudaGetSymbolAddress((void**)&s, g_s);

    const int GB = (NN + 63) / 64;           // gemm blocks (x)
    const int EB = (EE + 7) / 8;             // edge-warp blocks
    dim3 g1(GB, 1), g2(GB, 2);

    zero_init<<<4096, 256>>>(s);

    // h = x @ pre_W + pre_b
    {
        GArgs a{x, preW, preB, s->h};
        gemm64<FIN, false, false><<<g1, 128>>>(a, a, nullptr, NN);
    }

    // invariance branch (only layer 2 matters)
    scatter_ones<<<EB, 256>>>(row, col, s->h, s->Ai);
    {
        GArgs a{s->Ai, c3W1, c3b1, s->T1};
        gemm64<HID, true, true><<<g1, 128>>>(a, a, s->h, NN);
    }
    {
        GArgs a{s->T1, c3W2, c3b2, s->X1};
        gemm64<HID, false, true><<<g1, 128>>>(a, a, nullptr, NN);
    }

    // per-edge weights
    ew_kernel<<<EB, 256>>>(row, col, s->X1, s->ew);

    // exact top-k (k = 400000) radix select: 11 / 11 / 10 bits
    hist_kernel<<<1024, 256>>>(s->ew, s->hist, &s->st, 0);
    scan_kernel<<<1, 1024>>>(s->hist, &s->st, 2048, 11, 0);
    hist_kernel<<<1024, 256>>>(s->ew, s->hist, &s->st, 1);
    scan_kernel<<<1, 1024>>>(s->hist, &s->st, 2048, 11, 0);
    hist_kernel<<<1024, 256>>>(s->ew, s->hist, &s->st, 2);
    scan_kernel<<<1, 1024>>>(s->hist, &s->st, 1024, 10, 1);
    flag_kernel<<<2048, 256>>>(s->ew, s->flag, s->tie, &s->st);
    tie_resolve<<<1, 1024>>>(s->tie, s->flag, &s->st);

    // weighted scatters for both branches
    scatter_sel<<<EB, 256>>>(row, col, s->h, s->ew, s->flag, s->At, s->Ar);

    // dual-branch layer 1: T1 = relu((At+2h)@c1W1+b), T2 = relu((Ar+2h)@c4W1+b)
    {
        GArgs a{s->At, c1W1, c1b1, s->T1};
        GArgs b{s->Ar, c4W1, c4b1, s->T2};
        gemm64<HID, true, true><<<g2, 128>>>(a, b, s->h, NN);
    }
    // dual-branch layer 2: X1 = relu(T1@c1W2+b), X2 = relu(T2@c4W2+b)
    {
        GArgs a{s->T1, c1W2, c1b2, s->X1};
        GArgs b{s->T2, c4W2, c4b2, s->X2};
        gemm64<HID, false, true><<<g2, 128>>>(a, b, nullptr, NN);
    }

    // pool + head
    pool_kernel<<<(NN + NPB - 1) / NPB, HID>>>(s->X1, s->X2, batch, s->pool);
    head_kernel<<<NG, HID>>>(s->pool, postW, postB, roW, roB, out);
}